// round 5
// baseline (speedup 1.0000x reference)
#include <cuda_runtime.h>
#include <math.h>

// Problem dims
#define M_ROWS 16384      // B*S
#define KD     1024       // 2*DIM
#define NS     4096       // NSYM

// Scratch (device globals: allocation-free rule)
__device__ float  g_flat[(size_t)M_ROWS * KD];     // 67 MB
__device__ float  g_logits[(size_t)M_ROWS * NS];   // 256 MB (bias -> logits -> probs, in place)
__device__ float  g_Tt[(size_t)NS * NS];           // 67 MB  T^T
__device__ float  g_Mt[(size_t)NS * NS];           // 67 MB  M^T
__device__ float  g_cbT[(size_t)KD * NS];          // 16.8 MB codebook^T
__device__ float  g_rownorm[M_ROWS];
__device__ float  g_cbnorm[NS];
__device__ double g_sums[8];  // 0:sum_mag 1:sum_mag2 2:sum_d 3:sum_sigmeta 4:sum_gate 5:sum_align
__device__ float  g_c1;       // L2 * softplus(var/(1+eps))

__device__ __forceinline__ float sigmoidf_(float x) { return 1.0f / (1.0f + expf(-x)); }

__device__ double blockReduceD(double v, double* s) {
    int t = threadIdx.x;
    s[t] = v; __syncthreads();
    for (int k = blockDim.x >> 1; k > 0; k >>= 1) {
        if (t < k) s[t] += s[t + k];
        __syncthreads();
    }
    double r = s[0]; __syncthreads();
    return r;
}

__global__ void init_kernel() {
    int t = threadIdx.x;
    if (t < 8) g_sums[t] = 0.0;
}

// Build flat = [zr, zi], rownorm = ||flat||^2, global sums of mag and mag^2
__global__ __launch_bounds__(256) void prep_kernel(const float* __restrict__ zr,
                                                   const float* __restrict__ zi) {
    __shared__ double sred[256];
    int row = blockIdx.x, tid = threadIdx.x;
    double lm = 0.0, lm2 = 0.0;
#pragma unroll
    for (int t = 0; t < 2; t++) {
        int k = tid + t * 256;
        float a = zr[(size_t)row * 512 + k];
        float b = zi[(size_t)row * 512 + k];
        float m2 = a * a + b * b;
        g_flat[(size_t)row * KD + k]       = a;
        g_flat[(size_t)row * KD + 512 + k] = b;
        lm  += (double)sqrtf(m2);
        lm2 += (double)m2;
    }
    double rn = blockReduceD(lm2, sred);
    double sm = blockReduceD(lm, sred);
    if (tid == 0) {
        g_rownorm[row] = (float)rn;
        atomicAdd(&g_sums[0], sm);
        atomicAdd(&g_sums[1], rn);
    }
}

__global__ __launch_bounds__(256) void cbnorm_kernel(const float* __restrict__ cb) {
    __shared__ double sred[256];
    int n = blockIdx.x, tid = threadIdx.x;
    double s = 0.0;
#pragma unroll
    for (int t = 0; t < 4; t++) {
        float v = cb[(size_t)n * KD + tid + t * 256];
        s += (double)(v * v);
    }
    double r = blockReduceD(s, sred);
    if (tid == 0) g_cbnorm[n] = (float)r;
}

__global__ void c1_kernel() {
    const double Nm = 8388608.0; // B*S*DIM
    double s1 = g_sums[0], s2 = g_sums[1];
    double var = (s2 - s1 * s1 / Nm) / (Nm - 1.0);  // ddof=1
    double x = var / (1.0 + 1e-6);
    double sp = log1p(exp(x));                      // softplus
    g_c1 = (float)(0.01 * sp);                      // L2 * up_scalar
}

// Tiled transpose into template-selected global. in is R x C (row-major).
template <int DST>
__global__ void transpose_k(const float* __restrict__ in, int R, int C) {
    __shared__ float t[32][33];
    int x  = blockIdx.x * 32 + threadIdx.x;
    int y0 = blockIdx.y * 32;
    for (int i = threadIdx.y; i < 32; i += 8)
        t[i][threadIdx.x] = in[(size_t)(y0 + i) * C + x];
    __syncthreads();
    float* outp = (DST == 0) ? g_Tt : (DST == 1) ? g_Mt : g_cbT;
    int ox  = y0 + threadIdx.x;
    int oy0 = blockIdx.x * 32;
    for (int i = threadIdx.y; i < 32; i += 8)
        outp[(size_t)(oy0 + i) * R + ox] = t[threadIdx.x][i];
}

// NT GEMM: C[i,j] = sum_k A[i,k]*B[j,k]. 128x128 tile, BK=8, 256 thr, 8x8 micro.
// EP 0: g_logits = c1*sigmoid(acc)
// EP 1: reduce sum(sigmoid(acc)) -> g_sums[3]
// EP 2: d = rn+cn-2acc; g_logits = -(d - prev); sum d -> g_sums[2]
// EP 3: z_q store into out with layout mode (0 interleaved, 1 planar, 2 real-only)
template <int EP>
__global__ __launch_bounds__(256) void gemm_nt(const float* __restrict__ A,
                                               const float* __restrict__ B,
                                               int K, float* __restrict__ out,
                                               size_t out_n, int zqMode) {
    __shared__ __align__(16) float As[8][128];
    __shared__ __align__(16) float Bs[8][128];
    __shared__ double sred[256];
    int tid = threadIdx.x;
    int m0 = blockIdx.y * 128, n0 = blockIdx.x * 128;
    int lr = tid >> 1, lh = (tid & 1) * 4;
    int ty = tid >> 4, tx = tid & 15;

    float acc[8][8];
#pragma unroll
    for (int i = 0; i < 8; i++)
#pragma unroll
        for (int j = 0; j < 8; j++) acc[i][j] = 0.0f;

    const float* Ap = A + (size_t)(m0 + lr) * K + lh;
    const float* Bp = B + (size_t)(n0 + lr) * K + lh;

    for (int k0 = 0; k0 < K; k0 += 8) {
        float4 av = *(const float4*)(Ap + k0);
        float4 bv = *(const float4*)(Bp + k0);
        As[lh + 0][lr] = av.x; As[lh + 1][lr] = av.y; As[lh + 2][lr] = av.z; As[lh + 3][lr] = av.w;
        Bs[lh + 0][lr] = bv.x; Bs[lh + 1][lr] = bv.y; Bs[lh + 2][lr] = bv.z; Bs[lh + 3][lr] = bv.w;
        __syncthreads();
#pragma unroll
        for (int kk = 0; kk < 8; kk++) {
            float4 a0 = *(const float4*)&As[kk][ty * 8];
            float4 a1 = *(const float4*)&As[kk][ty * 8 + 4];
            float4 b0 = *(const float4*)&Bs[kk][tx * 8];
            float4 b1 = *(const float4*)&Bs[kk][tx * 8 + 4];
            float a8[8] = {a0.x, a0.y, a0.z, a0.w, a1.x, a1.y, a1.z, a1.w};
            float b8[8] = {b0.x, b0.y, b0.z, b0.w, b1.x, b1.y, b1.z, b1.w};
#pragma unroll
            for (int i = 0; i < 8; i++)
#pragma unroll
                for (int j = 0; j < 8; j++) acc[i][j] += a8[i] * b8[j];
        }
        __syncthreads();
    }

    int gr0 = m0 + ty * 8, gc0 = n0 + tx * 8;

    if (EP == 0) {
        float c1 = g_c1;
#pragma unroll
        for (int i = 0; i < 8; i++)
#pragma unroll
            for (int j = 0; j < 8; j++)
                g_logits[(size_t)(gr0 + i) * NS + gc0 + j] = c1 * sigmoidf_(acc[i][j]);
    } else if (EP == 1) {
        double s = 0.0;
#pragma unroll
        for (int i = 0; i < 8; i++)
#pragma unroll
            for (int j = 0; j < 8; j++) s += (double)sigmoidf_(acc[i][j]);
        double r = blockReduceD(s, sred);
        if (tid == 0) atomicAdd(&g_sums[3], r);
    } else if (EP == 2) {
        double s = 0.0;
#pragma unroll
        for (int i = 0; i < 8; i++) {
            float rn = g_rownorm[gr0 + i];
#pragma unroll
            for (int j = 0; j < 8; j++) {
                float cn = g_cbnorm[gc0 + j];
                size_t idx = (size_t)(gr0 + i) * NS + gc0 + j;
                float dv = rn + cn - 2.0f * acc[i][j];
                float prev = g_logits[idx];
                g_logits[idx] = -(dv - prev);
                s += (double)dv;
            }
        }
        double r = blockReduceD(s, sred);
        if (tid == 0) atomicAdd(&g_sums[2], r);
    } else { // EP == 3: z_q store
#pragma unroll
        for (int i = 0; i < 8; i++)
#pragma unroll
            for (int j = 0; j < 8; j++) {
                int gr = gr0 + i, gc = gc0 + j;
                size_t o;
                bool valid = true;
                if (zqMode == 0) { // interleaved complex
                    o = (gc < 512) ? ((size_t)gr * 512 + gc) * 2
                                   : ((size_t)gr * 512 + (gc - 512)) * 2 + 1;
                } else if (zqMode == 1) { // planar: real block then imag block
                    o = (gc < 512) ? ((size_t)gr * 512 + gc)
                                   : (8388608ULL + (size_t)gr * 512 + (gc - 512));
                } else { // real part only
                    valid = (gc < 512);
                    o = (size_t)gr * 512 + gc;
                }
                if (valid && o < out_n) out[o] = acc[i][j];
            }
    }
}

// Row-wise softmax / entropy / argmax / meta-gate accumulation.
// Probs written in place into g_logits; optional mirrors into out (offset-guarded).
__global__ __launch_bounds__(256) void softmax_kernel(const float* __restrict__ pent,
                                                      float* __restrict__ out,
                                                      size_t out_n,
                                                      size_t offProbs, size_t offHidx,
                                                      size_t offEnt) {
    __shared__ float sf[256];
    __shared__ float sv[256];
    __shared__ int   si[256];
    int row = blockIdx.x, tid = threadIdx.x;
    float* lrow = g_logits + (size_t)row * NS;

    float v[16];
    float mx = -3.4e38f;
#pragma unroll
    for (int t = 0; t < 16; t++) {
        v[t] = lrow[tid + t * 256];
        mx = fmaxf(mx, v[t]);
    }
    sf[tid] = mx; __syncthreads();
    for (int s = 128; s > 0; s >>= 1) { if (tid < s) sf[tid] = fmaxf(sf[tid], sf[tid + s]); __syncthreads(); }
    float rowmax = sf[0]; __syncthreads();

    float e[16]; float lsum = 0.0f;
#pragma unroll
    for (int t = 0; t < 16; t++) { e[t] = expf(v[t] - rowmax); lsum += e[t]; }
    sf[tid] = lsum; __syncthreads();
    for (int s = 128; s > 0; s >>= 1) { if (tid < s) sf[tid] += sf[tid + s]; __syncthreads(); }
    float rowsum = sf[0]; __syncthreads();

    float inv = 1.0f / rowsum;
    float ent = 0.0f, pm = -1.0f; int pidx = 0;
#pragma unroll
    for (int t = 0; t < 16; t++) {
        int col = tid + t * 256;
        float p = e[t] * inv;
        lrow[col] = p;                                  // in-place probs
        size_t oo = offProbs + (size_t)row * NS + col;
        if (oo < out_n) out[oo] = p;
        ent -= p * logf(p + 1e-9f);
        if (p > pm) { pm = p; pidx = col; }
    }
    sf[tid] = ent; __syncthreads();
    for (int s = 128; s > 0; s >>= 1) { if (tid < s) sf[tid] += sf[tid + s]; __syncthreads(); }
    float H = sf[0]; __syncthreads();

    sv[tid] = pm; si[tid] = pidx; __syncthreads();
    for (int s = 128; s > 0; s >>= 1) {
        if (tid < s) {
            if (sv[tid + s] > sv[tid] || (sv[tid + s] == sv[tid] && si[tid + s] < si[tid])) {
                sv[tid] = sv[tid + s]; si[tid] = si[tid + s];
            }
        }
        __syncthreads();
    }
    if (tid == 0) {
        if (offHidx + row < out_n) out[offHidx + row] = (float)si[0];
        if (offEnt + row < out_n)  out[offEnt + row]  = H;
        float dH = fabsf(H - pent[row]);
        float gate = sigmoidf_((dH - 0.5f) * 10.0f);
        atomicAdd(&g_sums[4], (double)gate);
    }
}

// anchors = probs @ EA, proj = flat @ W + b, accumulate mean((proj-anchor)^2)
__global__ __launch_bounds__(256) void anchor_kernel(const float* __restrict__ EA,
                                                     const float* __restrict__ W,
                                                     const float* __restrict__ bv) {
    __shared__ float sB[256 * 32];
    __shared__ double sred[256];
    int warp = threadIdx.x >> 5, lane = threadIdx.x & 31;
    int r0 = blockIdx.x * 32 + warp * 4;

    float accA[4] = {0.f, 0.f, 0.f, 0.f};
    for (int c = 0; c < NS; c += 256) {
        for (int i = threadIdx.x; i < 256 * 32; i += 256) sB[i] = EA[(size_t)c * 32 + i];
        __syncthreads();
        for (int n = 0; n < 256; n++) {
            float ea = sB[n * 32 + lane];
#pragma unroll
            for (int q = 0; q < 4; q++)
                accA[q] += g_logits[(size_t)(r0 + q) * NS + c + n] * ea;
        }
        __syncthreads();
    }

    float accP[4];
    float bb = bv[lane];
#pragma unroll
    for (int q = 0; q < 4; q++) accP[q] = bb;
    for (int c = 0; c < KD; c += 256) {
        for (int i = threadIdx.x; i < 256 * 32; i += 256) sB[i] = W[(size_t)c * 32 + i];
        __syncthreads();
        for (int k = 0; k < 256; k++) {
            float w = sB[k * 32 + lane];
#pragma unroll
            for (int q = 0; q < 4; q++)
                accP[q] += g_flat[(size_t)(r0 + q) * KD + c + k] * w;
        }
        __syncthreads();
    }

    double s = 0.0;
#pragma unroll
    for (int q = 0; q < 4; q++) {
        float df = accP[q] - accA[q];
        s += (double)(df * df);
    }
    double r = blockReduceD(s, sred);
    if (threadIdx.x == 0) atomicAdd(&g_sums[5], r);
}

__global__ void final_kernel(float* __restrict__ out, size_t out_n,
                             size_t offDmean, size_t offAlign, size_t offTrans) {
    const double MN = (double)M_ROWS * (double)NS;
    if (offDmean < out_n) out[offDmean] = (float)(g_sums[2] / MN);
    double gateMean = g_sums[4] / 16384.0;
    if (offTrans < out_n) out[offTrans] = (float)(gateMean * ((g_sums[2] - g_sums[3]) / MN));
    if (offAlign < out_n) out[offAlign] = (float)(g_sums[5] / (16384.0 * 32.0));
}

extern "C" void kernel_launch(void* const* d_in, const int* in_sizes, int n_in,
                              void* d_out, int out_size) {
    // ---- resolve inputs by element count; pairs in natural (dict) order ----
    int i8a = -1, i8b = -1, i16a = -1, i16b = -1;
    int iPSD = -1, iPE = -1, iCB = -1, iEA = -1, iW = -1, iB = -1;
    for (int i = 0; i < n_in; i++) {
        int s = in_sizes[i];
        if      (s == 8388608)  { if (i8a < 0) i8a = i; else i8b = i; }
        else if (s == 16777216) { if (i16a < 0) i16a = i; else i16b = i; }
        else if (s == 67108864) iPSD = i;
        else if (s == 16384)    iPE = i;
        else if (s == 4194304)  iCB = i;
        else if (s == 131072)   iEA = i;
        else if (s == 32768)    iW = i;
        else if (s == 32)       iB = i;
    }
    int iZR = i8a,  iZI = i8b;     // z_real first (dict order)
    int iT  = i16a, iMT = i16b;    // transition_matrix first

    const float* zr    = (const float*)d_in[iZR];
    const float* zi    = (const float*)d_in[iZI];
    const float* pprev = (const float*)d_in[iPSD];
    const float* pent  = (const float*)d_in[iPE];
    const float* cb    = (const float*)d_in[iCB];
    const float* T     = (const float*)d_in[iT];
    const float* EA    = (const float*)d_in[iEA];
    const float* W     = (const float*)d_in[iW];
    const float* bv    = (const float*)d_in[iB];
    const float* MT    = (const float*)d_in[iMT];
    float* out = (float*)d_out;
    size_t out_n = (size_t)(unsigned int)out_size;

    // ---- adaptive output layout based on out_size ----
    const size_t OFF_DISABLED = (size_t)1 << 62;
    int zqMode;                     // 0 interleaved, 1 planar, 2 real-only
    size_t offProbs, offHidx, offDmean, offEnt, offAlign, offTrans;
    bool full;
    if (out_n == 8388608ULL) {            // z_q real part only
        zqMode = 2; full = false;
        offProbs = offHidx = offDmean = offEnt = offAlign = offTrans = OFF_DISABLED;
    } else if (out_n == 16777216ULL) {    // z_q only, planar (interleaved disproven)
        zqMode = 1; full = false;
        offProbs = offHidx = offDmean = offEnt = offAlign = offTrans = OFF_DISABLED;
    } else if (out_n == 75530243ULL) {    // full tuple, z_q real-only
        zqMode = 2; full = true;
        offProbs = 8388608ULL;
        offHidx  = offProbs + 67108864ULL;   // 75497472
        offDmean = offHidx + 16384ULL;       // 75513856
        offEnt   = offDmean + 1ULL;          // 75513857
        offAlign = offEnt + 16384ULL;        // 75530241
        offTrans = offAlign + 1ULL;          // 75530242
    } else {                              // full tuple, interleaved complex z_q
        zqMode = 0; full = true;
        offProbs = 16777216ULL;
        offHidx  = offProbs + 67108864ULL;   // 83886080
        offDmean = offHidx + 16384ULL;       // 83902464
        offEnt   = offDmean + 1ULL;          // 83902465
        offAlign = offEnt + 16384ULL;        // 83918849
        offTrans = offAlign + 1ULL;          // 83918850
    }

    void *pTt = nullptr, *pMt = nullptr, *pcbT = nullptr, *pflat = nullptr, *plog = nullptr;
    cudaGetSymbolAddress(&pTt, g_Tt);
    cudaGetSymbolAddress(&pMt, g_Mt);
    cudaGetSymbolAddress(&pcbT, g_cbT);
    cudaGetSymbolAddress(&pflat, g_flat);
    cudaGetSymbolAddress(&plog, g_logits);

    init_kernel<<<1, 32>>>();
    prep_kernel<<<M_ROWS, 256>>>(zr, zi);
    cbnorm_kernel<<<NS, 256>>>(cb);
    c1_kernel<<<1, 1>>>();

    dim3 tb(32, 8);
    transpose_k<0><<<dim3(128, 128), tb>>>(T,  4096, 4096);
    if (full) transpose_k<1><<<dim3(128, 128), tb>>>(MT, 4096, 4096);
    transpose_k<2><<<dim3(32, 128),  tb>>>(cb, 4096, 1024);

    // graph bias -> g_logits = c1*sigmoid(gb)
    gemm_nt<0><<<dim3(32, 128), 256>>>(pprev, (const float*)pTt, 4096, nullptr, 0, 0);
    // meta bias -> sum sigmoid (only needed for transition_loss)
    if (full) gemm_nt<1><<<dim3(32, 128), 256>>>(pprev, (const float*)pMt, 4096, nullptr, 0, 0);
    // d + logits (in place over g_logits)
    gemm_nt<2><<<dim3(32, 128), 256>>>((const float*)pflat, cb, 1024, nullptr, 0, 0);
    // softmax / entropy / argmax / gate ; probs -> g_logits (+ mirrors, guarded)
    softmax_kernel<<<M_ROWS, 256>>>(pent, out, out_n, offProbs, offHidx, offEnt);
    // z_q = probs @ codebook
    gemm_nt<3><<<dim3(8, 128), 256>>>((const float*)plog, (const float*)pcbT, 4096, out, out_n, zqMode);
    // alignment + finalize (only needed for full tuple)
    if (full) {
        anchor_kernel<<<512, 256>>>(EA, W, bv);
        final_kernel<<<1, 1>>>(out, out_n, offDmean, offAlign, offTrans);
    }
}

// round 7
// speedup vs baseline: 2.8906x; 2.8906x over previous
#include <cuda_runtime.h>
#include <cuda_bf16.h>
#include <stdint.h>
#include <math.h>

// Problem dims
#define M_ROWS 16384      // B*S
#define KD     1024       // 2*DIM
#define NS     4096       // NSYM

// ---------------- scratch (device globals: allocation-free rule) ----------------
__device__ float  g_flat[(size_t)M_ROWS * KD];          // 67 MB
__device__ float  g_logits[(size_t)M_ROWS * NS];        // 268 MB (bias -> logits -> probs)
__device__ __nv_bfloat16 g_pB16[(size_t)M_ROWS * NS];   // 134 MB  prev_symbol_dist bf16
__device__ __nv_bfloat16 g_TtB16[(size_t)NS * NS];      // 33.5 MB T^T bf16
__device__ __nv_bfloat16 g_MtB16[(size_t)NS * NS];      // 33.5 MB M^T bf16
__device__ float  g_cbT[(size_t)KD * NS];               // 16.8 MB codebook^T fp32
__device__ float  g_rownorm[M_ROWS];
__device__ float  g_cbnorm[NS];
__device__ double g_sums[8];  // 0:sum_mag 1:sum_mag2 2:sum_d 3:sum_sigmeta 4:sum_gate 5:sum_align
__device__ float  g_c1;

__device__ __forceinline__ float sigmoidf_(float x) { return 1.0f / (1.0f + expf(-x)); }

__device__ double blockReduceD(double v, double* s) {
    int t = threadIdx.x;
    s[t] = v; __syncthreads();
    for (int k = blockDim.x >> 1; k > 0; k >>= 1) {
        if (t < k) s[t] += s[t + k];
        __syncthreads();
    }
    double r = s[0]; __syncthreads();
    return r;
}

__global__ void init_kernel() {
    int t = threadIdx.x;
    if (t < 8) g_sums[t] = 0.0;
}

__global__ __launch_bounds__(256) void prep_kernel(const float* __restrict__ zr,
                                                   const float* __restrict__ zi) {
    __shared__ double sred[256];
    int row = blockIdx.x, tid = threadIdx.x;
    double lm = 0.0, lm2 = 0.0;
#pragma unroll
    for (int t = 0; t < 2; t++) {
        int k = tid + t * 256;
        float a = zr[(size_t)row * 512 + k];
        float b = zi[(size_t)row * 512 + k];
        float m2 = a * a + b * b;
        g_flat[(size_t)row * KD + k]       = a;
        g_flat[(size_t)row * KD + 512 + k] = b;
        lm  += (double)sqrtf(m2);
        lm2 += (double)m2;
    }
    double rn = blockReduceD(lm2, sred);
    double sm = blockReduceD(lm, sred);
    if (tid == 0) {
        g_rownorm[row] = (float)rn;
        atomicAdd(&g_sums[0], sm);
        atomicAdd(&g_sums[1], rn);
    }
}

__global__ __launch_bounds__(256) void cbnorm_kernel(const float* __restrict__ cb) {
    __shared__ double sred[256];
    int n = blockIdx.x, tid = threadIdx.x;
    double s = 0.0;
#pragma unroll
    for (int t = 0; t < 4; t++) {
        float v = cb[(size_t)n * KD + tid + t * 256];
        s += (double)(v * v);
    }
    double r = blockReduceD(s, sred);
    if (tid == 0) g_cbnorm[n] = (float)r;
}

__global__ void c1_kernel() {
    const double Nm = 8388608.0;
    double s1 = g_sums[0], s2 = g_sums[1];
    double var = (s2 - s1 * s1 / Nm) / (Nm - 1.0);
    double x = var / (1.0 + 1e-6);
    g_c1 = (float)(0.01 * log1p(exp(x)));
}

// fp32 -> bf16 straight conversion (p), 4 elems/thread
__global__ __launch_bounds__(256) void conv_p_kernel(const float* __restrict__ in) {
    size_t i = (size_t)blockIdx.x * 256 + threadIdx.x;   // over n/4
    float4 v = ((const float4*)in)[i];
    __nv_bfloat162 lo = __floats2bfloat162_rn(v.x, v.y);
    __nv_bfloat162 hi = __floats2bfloat162_rn(v.z, v.w);
    uint2 u;
    u.x = *(uint32_t*)&lo;
    u.y = *(uint32_t*)&hi;
    ((uint2*)g_pB16)[i] = u;
}

// transpose 4096x4096 fp32 -> bf16 into g_TtB16 (DST=0) / g_MtB16 (DST=1)
template <int DST>
__global__ void transpose_bf16(const float* __restrict__ in) {
    __shared__ float t[32][33];
    int x  = blockIdx.x * 32 + threadIdx.x;
    int y0 = blockIdx.y * 32;
    for (int i = threadIdx.y; i < 32; i += 8)
        t[i][threadIdx.x] = in[(size_t)(y0 + i) * NS + x];
    __syncthreads();
    __nv_bfloat16* outp = DST ? g_MtB16 : g_TtB16;
    int ox  = y0 + threadIdx.x;
    int oy0 = blockIdx.x * 32;
    for (int i = threadIdx.y; i < 32; i += 8)
        outp[(size_t)(oy0 + i) * NS + ox] = __float2bfloat16(t[threadIdx.x][i]);
}

// transpose codebook 4096x1024 fp32 -> g_cbT fp32 (for z_q gemm)
__global__ void transpose_cb(const float* __restrict__ in) {
    __shared__ float t[32][33];
    int x  = blockIdx.x * 32 + threadIdx.x;
    int y0 = blockIdx.y * 32;
    for (int i = threadIdx.y; i < 32; i += 8)
        t[i][threadIdx.x] = in[(size_t)(y0 + i) * KD + x];
    __syncthreads();
    int ox  = y0 + threadIdx.x;
    int oy0 = blockIdx.x * 32;
    for (int i = threadIdx.y; i < 32; i += 8)
        g_cbT[(size_t)(oy0 + i) * NS + ox] = t[threadIdx.x][i];
}

// ---------------- HMMA bf16 GEMM for the two bias matmuls (mma.sync path) ----------------
// C[m,n] = sum_k A[m,k]*B[n,k]; A = g_pB16 [16384,4096], B = Tt/Mt bf16 [4096,4096].
// Block tile 128x128, BK=64, 8 warps (2 warp_m x 4 warp_n), warp tile 64x32.
// EP 0: g_logits[m,n] = c1 * sigmoid(acc);  EP 1: g_sums[3] += sum(sigmoid(acc))
__device__ __forceinline__ void mma16816(float* c, uint32_t a0, uint32_t a1, uint32_t a2,
                                         uint32_t a3, uint32_t b0, uint32_t b1) {
    asm volatile(
        "mma.sync.aligned.m16n8k16.row.col.f32.bf16.bf16.f32 "
        "{%0,%1,%2,%3}, {%4,%5,%6,%7}, {%8,%9}, {%0,%1,%2,%3};"
        : "+f"(c[0]), "+f"(c[1]), "+f"(c[2]), "+f"(c[3])
        : "r"(a0), "r"(a1), "r"(a2), "r"(a3), "r"(b0), "r"(b1));
}
// smem tile: 128 rows x 64 bf16 (128B row = 8 x 16B chunks), chunk XOR-swizzled by row&7
__device__ __forceinline__ uint32_t tile_word(const uint8_t* s, int r, int w) {
    return *(const uint32_t*)(s + r * 128 + ((((w >> 2) ^ (r & 7)) << 4) | ((w & 3) << 2)));
}

template <int EP>
__global__ __launch_bounds__(256) void gemm_bias_mma(const __nv_bfloat16* __restrict__ A,
                                                     const __nv_bfloat16* __restrict__ B) {
    __shared__ __align__(16) uint8_t As[128 * 128];
    __shared__ __align__(16) uint8_t Bs[128 * 128];
    int tid = threadIdx.x, lane = tid & 31, wid = tid >> 5;
    int wm = wid & 1, wn = wid >> 1;               // 2 x 4 warps
    int m0 = blockIdx.y * 128, n0 = blockIdx.x * 128;

    float acc[4][4][4];
#pragma unroll
    for (int i = 0; i < 4; i++)
#pragma unroll
        for (int j = 0; j < 4; j++)
#pragma unroll
            for (int k = 0; k < 4; k++) acc[i][j][k] = 0.0f;

    const uint4* gA = (const uint4*)A;   // row = 512 uint4
    const uint4* gB = (const uint4*)B;

    for (int it = 0; it < 64; it++) {
#pragma unroll
        for (int l = 0; l < 4; l++) {
            int i = tid + l * 256;          // 0..1023
            int r = i >> 3, c = i & 7;
            uint32_t d = r * 128 + (((c ^ (r & 7))) << 4);
            *(uint4*)(As + d) = gA[(size_t)(m0 + r) * 512 + it * 8 + c];
            *(uint4*)(Bs + d) = gB[(size_t)(n0 + r) * 512 + it * 8 + c];
        }
        __syncthreads();
#pragma unroll
        for (int ks = 0; ks < 4; ks++) {
            int w  = ks * 8 + (lane & 3);
            int w2 = w + 4;
            uint32_t bf[4][2];
#pragma unroll
            for (int nt = 0; nt < 4; nt++) {
                int br = wn * 32 + nt * 8 + (lane >> 2);
                bf[nt][0] = tile_word(Bs, br, w);
                bf[nt][1] = tile_word(Bs, br, w2);
            }
#pragma unroll
            for (int mt = 0; mt < 4; mt++) {
                int ar0 = wm * 64 + mt * 16 + (lane >> 2);
                int ar1 = ar0 + 8;
                uint32_t a0 = tile_word(As, ar0, w);
                uint32_t a1 = tile_word(As, ar1, w);
                uint32_t a2 = tile_word(As, ar0, w2);
                uint32_t a3 = tile_word(As, ar1, w2);
#pragma unroll
                for (int nt = 0; nt < 4; nt++)
                    mma16816(acc[mt][nt], a0, a1, a2, a3, bf[nt][0], bf[nt][1]);
            }
        }
        __syncthreads();
    }

    // epilogue
    if (EP == 0) {
        float c1v = g_c1;
#pragma unroll
        for (int mt = 0; mt < 4; mt++) {
            int gr = m0 + wm * 64 + mt * 16 + (lane >> 2);
#pragma unroll
            for (int nt = 0; nt < 4; nt++) {
                int gc = n0 + wn * 32 + nt * 8 + (lane & 3) * 2;
                float* d0 = g_logits + (size_t)gr * NS + gc;
                float* d1 = g_logits + (size_t)(gr + 8) * NS + gc;
                d0[0] = c1v * sigmoidf_(acc[mt][nt][0]);
                d0[1] = c1v * sigmoidf_(acc[mt][nt][1]);
                d1[0] = c1v * sigmoidf_(acc[mt][nt][2]);
                d1[1] = c1v * sigmoidf_(acc[mt][nt][3]);
            }
        }
    } else {
        float s = 0.0f;
#pragma unroll
        for (int mt = 0; mt < 4; mt++)
#pragma unroll
            for (int nt = 0; nt < 4; nt++)
#pragma unroll
                for (int k = 0; k < 4; k++) s += sigmoidf_(acc[mt][nt][k]);
        double ds = (double)s;
#pragma unroll
        for (int o = 16; o > 0; o >>= 1)
            ds += __shfl_down_sync(0xffffffff, ds, o);
        if (lane == 0) atomicAdd(&g_sums[3], ds);
    }
}

// ---------------- fp32 SIMT NT GEMM (d and z_q) ----------------
// EP 2: d = rn+cn-2acc; g_logits = -(d - prev); sum d -> g_sums[2]
// EP 3: z_q store into out (mode 0 interleaved / 1 planar / 2 real-only), guarded
template <int EP>
__global__ __launch_bounds__(256) void gemm_nt(const float* __restrict__ A,
                                               const float* __restrict__ B,
                                               int K, float* __restrict__ out,
                                               size_t out_n, int zqMode) {
    __shared__ __align__(16) float As[8][128];
    __shared__ __align__(16) float Bs[8][128];
    __shared__ double sred[256];
    int tid = threadIdx.x;
    int m0 = blockIdx.y * 128, n0 = blockIdx.x * 128;
    int lr = tid >> 1, lh = (tid & 1) * 4;
    int ty = tid >> 4, tx = tid & 15;

    float acc[8][8];
#pragma unroll
    for (int i = 0; i < 8; i++)
#pragma unroll
        for (int j = 0; j < 8; j++) acc[i][j] = 0.0f;

    const float* Ap = A + (size_t)(m0 + lr) * K + lh;
    const float* Bp = B + (size_t)(n0 + lr) * K + lh;

    for (int k0 = 0; k0 < K; k0 += 8) {
        float4 av = *(const float4*)(Ap + k0);
        float4 bv = *(const float4*)(Bp + k0);
        As[lh + 0][lr] = av.x; As[lh + 1][lr] = av.y; As[lh + 2][lr] = av.z; As[lh + 3][lr] = av.w;
        Bs[lh + 0][lr] = bv.x; Bs[lh + 1][lr] = bv.y; Bs[lh + 2][lr] = bv.z; Bs[lh + 3][lr] = bv.w;
        __syncthreads();
#pragma unroll
        for (int kk = 0; kk < 8; kk++) {
            float4 a0 = *(const float4*)&As[kk][ty * 8];
            float4 a1 = *(const float4*)&As[kk][ty * 8 + 4];
            float4 b0 = *(const float4*)&Bs[kk][tx * 8];
            float4 b1 = *(const float4*)&Bs[kk][tx * 8 + 4];
            float a8[8] = {a0.x, a0.y, a0.z, a0.w, a1.x, a1.y, a1.z, a1.w};
            float b8[8] = {b0.x, b0.y, b0.z, b0.w, b1.x, b1.y, b1.z, b1.w};
#pragma unroll
            for (int i = 0; i < 8; i++)
#pragma unroll
                for (int j = 0; j < 8; j++) acc[i][j] += a8[i] * b8[j];
        }
        __syncthreads();
    }

    int gr0 = m0 + ty * 8, gc0 = n0 + tx * 8;

    if (EP == 2) {
        double s = 0.0;
#pragma unroll
        for (int i = 0; i < 8; i++) {
            float rn = g_rownorm[gr0 + i];
#pragma unroll
            for (int j = 0; j < 8; j++) {
                float cn = g_cbnorm[gc0 + j];
                size_t idx = (size_t)(gr0 + i) * NS + gc0 + j;
                float dv = rn + cn - 2.0f * acc[i][j];
                float prev = g_logits[idx];
                g_logits[idx] = -(dv - prev);
                s += (double)dv;
            }
        }
        double r = blockReduceD(s, sred);
        if (tid == 0) atomicAdd(&g_sums[2], r);
    } else { // EP == 3
#pragma unroll
        for (int i = 0; i < 8; i++)
#pragma unroll
            for (int j = 0; j < 8; j++) {
                int gr = gr0 + i, gc = gc0 + j;
                size_t o;
                bool valid = true;
                if (zqMode == 0) {
                    o = (gc < 512) ? ((size_t)gr * 512 + gc) * 2
                                   : ((size_t)gr * 512 + (gc - 512)) * 2 + 1;
                } else if (zqMode == 1) {
                    o = (gc < 512) ? ((size_t)gr * 512 + gc)
                                   : (8388608ULL + (size_t)gr * 512 + (gc - 512));
                } else {
                    valid = (gc < 512);
                    o = (size_t)gr * 512 + gc;
                }
                if (valid && o < out_n) out[o] = acc[i][j];
            }
    }
}

// ---------------- softmax / entropy / argmax / gate ----------------
__global__ __launch_bounds__(256) void softmax_kernel(const float* __restrict__ pent,
                                                      float* __restrict__ out,
                                                      size_t out_n,
                                                      size_t offProbs, size_t offHidx,
                                                      size_t offEnt) {
    __shared__ float sf[256];
    __shared__ float sv[256];
    __shared__ int   si[256];
    int row = blockIdx.x, tid = threadIdx.x;
    float* lrow = g_logits + (size_t)row * NS;

    float v[16];
    float mx = -3.4e38f;
#pragma unroll
    for (int t = 0; t < 16; t++) {
        v[t] = lrow[tid + t * 256];
        mx = fmaxf(mx, v[t]);
    }
    sf[tid] = mx; __syncthreads();
    for (int s = 128; s > 0; s >>= 1) { if (tid < s) sf[tid] = fmaxf(sf[tid], sf[tid + s]); __syncthreads(); }
    float rowmax = sf[0]; __syncthreads();

    float e[16]; float lsum = 0.0f;
#pragma unroll
    for (int t = 0; t < 16; t++) { e[t] = expf(v[t] - rowmax); lsum += e[t]; }
    sf[tid] = lsum; __syncthreads();
    for (int s = 128; s > 0; s >>= 1) { if (tid < s) sf[tid] += sf[tid + s]; __syncthreads(); }
    float rowsum = sf[0]; __syncthreads();

    float inv = 1.0f / rowsum;
    float ent = 0.0f, pm = -1.0f; int pidx = 0;
#pragma unroll
    for (int t = 0; t < 16; t++) {
        int col = tid + t * 256;
        float p = e[t] * inv;
        lrow[col] = p;
        size_t oo = offProbs + (size_t)row * NS + col;
        if (oo < out_n) out[oo] = p;
        ent -= p * logf(p + 1e-9f);
        if (p > pm) { pm = p; pidx = col; }
    }
    sf[tid] = ent; __syncthreads();
    for (int s = 128; s > 0; s >>= 1) { if (tid < s) sf[tid] += sf[tid + s]; __syncthreads(); }
    float H = sf[0]; __syncthreads();

    sv[tid] = pm; si[tid] = pidx; __syncthreads();
    for (int s = 128; s > 0; s >>= 1) {
        if (tid < s) {
            if (sv[tid + s] > sv[tid] || (sv[tid + s] == sv[tid] && si[tid + s] < si[tid])) {
                sv[tid] = sv[tid + s]; si[tid] = si[tid + s];
            }
        }
        __syncthreads();
    }
    if (tid == 0) {
        if (offHidx + row < out_n) out[offHidx + row] = (float)si[0];
        if (offEnt + row < out_n)  out[offEnt + row]  = H;
        float dH = fabsf(H - pent[row]);
        float gate = sigmoidf_((dH - 0.5f) * 10.0f);
        atomicAdd(&g_sums[4], (double)gate);
    }
}

// ---------------- anchor alignment loss ----------------
__global__ __launch_bounds__(256) void anchor_kernel(const float* __restrict__ EA,
                                                     const float* __restrict__ W,
                                                     const float* __restrict__ bv) {
    __shared__ float sB[256 * 32];
    __shared__ double sred[256];
    int warp = threadIdx.x >> 5, lane = threadIdx.x & 31;
    int r0 = blockIdx.x * 32 + warp * 4;

    float accA[4] = {0.f, 0.f, 0.f, 0.f};
    for (int c = 0; c < NS; c += 256) {
        for (int i = threadIdx.x; i < 256 * 32; i += 256) sB[i] = EA[(size_t)c * 32 + i];
        __syncthreads();
        for (int n = 0; n < 256; n++) {
            float ea = sB[n * 32 + lane];
#pragma unroll
            for (int q = 0; q < 4; q++)
                accA[q] += g_logits[(size_t)(r0 + q) * NS + c + n] * ea;
        }
        __syncthreads();
    }

    float accP[4];
    float bb = bv[lane];
#pragma unroll
    for (int q = 0; q < 4; q++) accP[q] = bb;
    for (int c = 0; c < KD; c += 256) {
        for (int i = threadIdx.x; i < 256 * 32; i += 256) sB[i] = W[(size_t)c * 32 + i];
        __syncthreads();
        for (int k = 0; k < 256; k++) {
            float w = sB[k * 32 + lane];
#pragma unroll
            for (int q = 0; q < 4; q++)
                accP[q] += g_flat[(size_t)(r0 + q) * KD + c + k] * w;
        }
        __syncthreads();
    }

    double s = 0.0;
#pragma unroll
    for (int q = 0; q < 4; q++) {
        float df = accP[q] - accA[q];
        s += (double)(df * df);
    }
    double r = blockReduceD(s, sred);
    if (threadIdx.x == 0) atomicAdd(&g_sums[5], r);
}

__global__ void final_kernel(float* __restrict__ out, size_t out_n,
                             size_t offDmean, size_t offAlign, size_t offTrans) {
    const double MN = (double)M_ROWS * (double)NS;
    if (offDmean < out_n) out[offDmean] = (float)(g_sums[2] / MN);
    double gateMean = g_sums[4] / 16384.0;
    if (offTrans < out_n) out[offTrans] = (float)(gateMean * ((g_sums[2] - g_sums[3]) / MN));
    if (offAlign < out_n) out[offAlign] = (float)(g_sums[5] / (16384.0 * 32.0));
}

// ---------------- host launcher ----------------
extern "C" void kernel_launch(void* const* d_in, const int* in_sizes, int n_in,
                              void* d_out, int out_size) {
    int i8a = -1, i8b = -1, i16a = -1, i16b = -1;
    int iPSD = -1, iPE = -1, iCB = -1, iEA = -1, iW = -1, iB = -1;
    for (int i = 0; i < n_in; i++) {
        int s = in_sizes[i];
        if      (s == 8388608)  { if (i8a < 0) i8a = i; else i8b = i; }
        else if (s == 16777216) { if (i16a < 0) i16a = i; else i16b = i; }
        else if (s == 67108864) iPSD = i;
        else if (s == 16384)    iPE = i;
        else if (s == 4194304)  iCB = i;
        else if (s == 131072)   iEA = i;
        else if (s == 32768)    iW = i;
        else if (s == 32)       iB = i;
    }
    const float* zr    = (const float*)d_in[i8a];
    const float* zi    = (const float*)d_in[i8b];
    const float* pprev = (const float*)d_in[iPSD];
    const float* pent  = (const float*)d_in[iPE];
    const float* cb    = (const float*)d_in[iCB];
    const float* T     = (const float*)d_in[i16a];
    const float* EA    = (const float*)d_in[iEA];
    const float* W     = (const float*)d_in[iW];
    const float* bv    = (const float*)d_in[iB];
    const float* MT    = (const float*)d_in[i16b];
    float* out = (float*)d_out;
    size_t out_n = (size_t)(unsigned int)out_size;

    // adaptive output layout (R5 confirmed: full tuple + interleaved complex)
    const size_t OFF_DISABLED = (size_t)1 << 62;
    int zqMode; bool full;
    size_t offProbs, offHidx, offDmean, offEnt, offAlign, offTrans;
    if (out_n == 8388608ULL) {
        zqMode = 2; full = false;
        offProbs = offHidx = offDmean = offEnt = offAlign = offTrans = OFF_DISABLED;
    } else if (out_n == 16777216ULL) {
        zqMode = 1; full = false;
        offProbs = offHidx = offDmean = offEnt = offAlign = offTrans = OFF_DISABLED;
    } else if (out_n == 75530243ULL) {
        zqMode = 2; full = true;
        offProbs = 8388608ULL;
        offHidx  = offProbs + 67108864ULL;
        offDmean = offHidx + 16384ULL;
        offEnt   = offDmean + 1ULL;
        offAlign = offEnt + 16384ULL;
        offTrans = offAlign + 1ULL;
    } else {
        zqMode = 0; full = true;
        offProbs = 16777216ULL;
        offHidx  = offProbs + 67108864ULL;
        offDmean = offHidx + 16384ULL;
        offEnt   = offDmean + 1ULL;
        offAlign = offEnt + 16384ULL;
        offTrans = offAlign + 1ULL;
    }

    void *pflat = nullptr, *plog = nullptr, *pcbT = nullptr, *ppB16 = nullptr,
         *pTtB = nullptr, *pMtB = nullptr;
    cudaGetSymbolAddress(&pflat, g_flat);
    cudaGetSymbolAddress(&plog, g_logits);
    cudaGetSymbolAddress(&pcbT, g_cbT);
    cudaGetSymbolAddress(&ppB16, g_pB16);
    cudaGetSymbolAddress(&pTtB, g_TtB16);
    cudaGetSymbolAddress(&pMtB, g_MtB16);

    init_kernel<<<1, 32>>>();
    prep_kernel<<<M_ROWS, 256>>>(zr, zi);
    cbnorm_kernel<<<NS, 256>>>(cb);
    c1_kernel<<<1, 1>>>();

    // bf16 conversions for tensor-core bias GEMMs
    conv_p_kernel<<<65536, 256>>>(pprev);
    dim3 tb(32, 8);
    transpose_bf16<0><<<dim3(128, 128), tb>>>(T);
    if (full) transpose_bf16<1><<<dim3(128, 128), tb>>>(MT);
    transpose_cb<<<dim3(32, 128), tb>>>(cb);

    // graph bias: g_logits = c1*sigmoid(p @ T)   [HMMA bf16]
    gemm_bias_mma<0><<<dim3(32, 128), 256>>>(
        (const __nv_bfloat16*)ppB16, (const __nv_bfloat16*)pTtB);
    // meta bias: sum sigmoid(p @ M)              [HMMA bf16]
    if (full)
        gemm_bias_mma<1><<<dim3(32, 128), 256>>>(
            (const __nv_bfloat16*)ppB16, (const __nv_bfloat16*)pMtB);

    // d + logits (fp32 SIMT)
    gemm_nt<2><<<dim3(32, 128), 256>>>((const float*)pflat, cb, 1024, nullptr, 0, 0);
    // softmax / entropy / argmax / gate
    softmax_kernel<<<M_ROWS, 256>>>(pent, out, out_n, offProbs, offHidx, offEnt);
    // z_q = probs @ codebook (fp32 SIMT)
    gemm_nt<3><<<dim3(8, 128), 256>>>((const float*)plog, (const float*)pcbT, 4096, out, out_n, zqMode);

    if (full) {
        anchor_kernel<<<512, 256>>>(EA, W, bv);
        final_kernel<<<1, 1>>>(out, out_n, offDmean, offAlign, offTrans);
    }
}

// round 10
// speedup vs baseline: 5.8010x; 2.0069x over previous
#include <cuda_runtime.h>
#include <cuda_bf16.h>
#include <stdint.h>
#include <math.h>

#define M_ROWS 16384
#define KD     1024
#define NS     4096

// ---------------- scratch (device globals) ----------------
__device__ float  g_flat[(size_t)M_ROWS * KD];            // 67 MB (anchor proj)
__device__ float  g_logits[(size_t)M_ROWS * NS];          // 268 MB (bias -> logits)
__device__ __nv_bfloat16 g_pB16[(size_t)M_ROWS * NS];     // 134 MB prev_symbol_dist bf16
__device__ __nv_bfloat16 g_TtB16[(size_t)NS * NS];        // 33.5 MB T^T bf16
__device__ __nv_bfloat16 g_MtB16[(size_t)NS * NS];        // 33.5 MB M^T bf16
__device__ __nv_bfloat16 g_A3d[(size_t)M_ROWS * 3072];    // 100 MB [flat_hi|flat_lo|flat_hi]
__device__ __nv_bfloat16 g_B3d[(size_t)NS * 3072];        // 25 MB  [cb_hi|cb_hi|cb_lo]
__device__ __nv_bfloat16 g_A3z[(size_t)M_ROWS * 12288];   // 403 MB [p_hi|p_lo|p_hi]
__device__ __nv_bfloat16 g_B3z[(size_t)KD * 12288];       // 25 MB  [cbT_hi|cbT_hi|cbT_lo]
__device__ float  g_rownorm[M_ROWS];
__device__ float  g_cbnorm[NS];
__device__ double g_sums[8];
__device__ float  g_c1;

__device__ __forceinline__ float sigmoidf_(float x) { return 1.0f / (1.0f + expf(-x)); }
__device__ __forceinline__ void split_bf16(float x, __nv_bfloat16& hi, __nv_bfloat16& lo) {
    hi = __float2bfloat16(x);
    lo = __float2bfloat16(x - __bfloat162float(hi));
}

__device__ double blockReduceD(double v, double* s) {
    int t = threadIdx.x;
    s[t] = v; __syncthreads();
    for (int k = blockDim.x >> 1; k > 0; k >>= 1) {
        if (t < k) s[t] += s[t + k];
        __syncthreads();
    }
    double r = s[0]; __syncthreads();
    return r;
}

__global__ void init_kernel() {
    if (threadIdx.x < 8) g_sums[threadIdx.x] = 0.0;
}

// flat = [zr,zi]; rownorm; mag sums; A3d = [hi|lo|hi]
__global__ __launch_bounds__(256) void prep_kernel(const float* __restrict__ zr,
                                                   const float* __restrict__ zi) {
    __shared__ double sred[256];
    int row = blockIdx.x, tid = threadIdx.x;
    size_t fb = (size_t)row * KD, ab = (size_t)row * 3072;
    double lm = 0.0, lm2 = 0.0;
#pragma unroll
    for (int t = 0; t < 2; t++) {
        int k = tid + t * 256;
        float a = zr[(size_t)row * 512 + k];
        float b = zi[(size_t)row * 512 + k];
        float m2 = a * a + b * b;
        g_flat[fb + k]       = a;
        g_flat[fb + 512 + k] = b;
        __nv_bfloat16 hi, lo;
        split_bf16(a, hi, lo);
        g_A3d[ab + k] = hi; g_A3d[ab + 2048 + k] = hi; g_A3d[ab + 1024 + k] = lo;
        split_bf16(b, hi, lo);
        g_A3d[ab + 512 + k] = hi; g_A3d[ab + 2560 + k] = hi; g_A3d[ab + 1536 + k] = lo;
        lm  += (double)sqrtf(m2);
        lm2 += (double)m2;
    }
    double rn = blockReduceD(lm2, sred);
    double sm = blockReduceD(lm, sred);
    if (tid == 0) {
        g_rownorm[row] = (float)rn;
        atomicAdd(&g_sums[0], sm);
        atomicAdd(&g_sums[1], rn);
    }
}

// cbnorm + B3d rows [hi|hi|lo]
__global__ __launch_bounds__(256) void cb_rows_kernel(const float* __restrict__ cb) {
    __shared__ double sred[256];
    int n = blockIdx.x, tid = threadIdx.x;
    size_t bb = (size_t)n * 3072;
    double s = 0.0;
#pragma unroll
    for (int t = 0; t < 4; t++) {
        int k = tid + t * 256;
        float v = cb[(size_t)n * KD + k];
        s += (double)(v * v);
        __nv_bfloat16 hi, lo;
        split_bf16(v, hi, lo);
        g_B3d[bb + k] = hi; g_B3d[bb + 1024 + k] = hi; g_B3d[bb + 2048 + k] = lo;
    }
    double r = blockReduceD(s, sred);
    if (tid == 0) g_cbnorm[n] = (float)r;
}

__global__ void c1_kernel() {
    const double Nm = 8388608.0;
    double s1 = g_sums[0], s2 = g_sums[1];
    double var = (s2 - s1 * s1 / Nm) / (Nm - 1.0);
    double x = var / (1.0 + 1e-6);
    g_c1 = (float)(0.01 * log1p(exp(x)));
}

// p fp32 -> bf16
__global__ __launch_bounds__(256) void conv_p_kernel(const float* __restrict__ in) {
    size_t i = (size_t)blockIdx.x * 256 + threadIdx.x;
    float4 v = ((const float4*)in)[i];
    __nv_bfloat162 lo = __floats2bfloat162_rn(v.x, v.y);
    __nv_bfloat162 hi = __floats2bfloat162_rn(v.z, v.w);
    uint2 u; u.x = *(uint32_t*)&lo; u.y = *(uint32_t*)&hi;
    ((uint2*)g_pB16)[i] = u;
}

// transpose 4096x4096 fp32 -> bf16 (T^T / M^T)
template <int DST>
__global__ void transpose_bf16(const float* __restrict__ in) {
    __shared__ float t[32][33];
    int x  = blockIdx.x * 32 + threadIdx.x;
    int y0 = blockIdx.y * 32;
    for (int i = threadIdx.y; i < 32; i += 8)
        t[i][threadIdx.x] = in[(size_t)(y0 + i) * NS + x];
    __syncthreads();
    __nv_bfloat16* outp = DST ? g_MtB16 : g_TtB16;
    int ox  = y0 + threadIdx.x;
    int oy0 = blockIdx.x * 32;
    for (int i = threadIdx.y; i < 32; i += 8)
        outp[(size_t)(oy0 + i) * NS + ox] = __float2bfloat16(t[threadIdx.x][i]);
}

// transpose cb [4096,1024] -> B3z [1024, 12288] = [cbT_hi|cbT_hi|cbT_lo]
// FIXED (R8 bug): value must be t[threadIdx.x][i] (true transpose), matching R7's
// proven transpose_cb: output row = blockIdx.x*32+i (cb col), col = y0+threadIdx.x (cb row).
__global__ void transpose_cb_split(const float* __restrict__ in) {
    __shared__ float t[32][33];
    int x  = blockIdx.x * 32 + threadIdx.x;   // col of cb (0..1023)
    int y0 = blockIdx.y * 32;                 // row base of cb (0..4095)
    for (int i = threadIdx.y; i < 32; i += 8)
        t[i][threadIdx.x] = in[(size_t)(y0 + i) * KD + x];
    __syncthreads();
    int ox  = y0 + threadIdx.x;               // output col = cb row
    int oy0 = blockIdx.x * 32;                // output row base = cb col base
    for (int i = threadIdx.y; i < 32; i += 8) {
        float v = t[threadIdx.x][i];          // = cb[y0+tx][bx*32+i] = cbT[oy0+i][ox]
        __nv_bfloat16 hi, lo;
        split_bf16(v, hi, lo);
        size_t base = (size_t)(oy0 + i) * 12288;
        g_B3z[base + ox] = hi; g_B3z[base + 4096 + ox] = hi; g_B3z[base + 8192 + ox] = lo;
    }
}

// ---------------- pipelined HMMA bf16 NT GEMM ----------------
// C[i,j] = sum_k A[i,k]*B[j,k]. Block 128x128, BK=64, 8 warps (2x4), cp.async 2-stage.
// EP0 bias-store: g_logits = c1*sigmoid(acc)
// EP1 bias-sum:   g_sums[3] += sum sigmoid(acc)
// EP2 d-epilogue: d = rn+cn-2acc; g_logits = -(d-prev); g_sums[2] += sum d
// EP3 zq-store:   interleaved complex into out
__device__ __forceinline__ void mma16816(float* c, uint32_t a0, uint32_t a1, uint32_t a2,
                                         uint32_t a3, uint32_t b0, uint32_t b1) {
    asm volatile(
        "mma.sync.aligned.m16n8k16.row.col.f32.bf16.bf16.f32 "
        "{%0,%1,%2,%3}, {%4,%5,%6,%7}, {%8,%9}, {%0,%1,%2,%3};"
        : "+f"(c[0]), "+f"(c[1]), "+f"(c[2]), "+f"(c[3])
        : "r"(a0), "r"(a1), "r"(a2), "r"(a3), "r"(b0), "r"(b1));
}
__device__ __forceinline__ uint32_t tile_word(const uint8_t* s, int r, int w) {
    return *(const uint32_t*)(s + r * 128 + ((((w >> 2) ^ (r & 7)) << 4) | ((w & 3) << 2)));
}
__device__ __forceinline__ void cp16(void* s, const void* g) {
    uint32_t sa = (uint32_t)__cvta_generic_to_shared(s);
    asm volatile("cp.async.cg.shared.global [%0], [%1], 16;" :: "r"(sa), "l"(g) : "memory");
}
__device__ __forceinline__ void load_tiles(uint8_t* As, uint8_t* Bs,
                                           const uint4* gA, const uint4* gB,
                                           int m0, int n0, int Kv, int it, int tid) {
#pragma unroll
    for (int l = 0; l < 4; l++) {
        int i = tid + l * 256;
        int r = i >> 3, c = i & 7;
        uint32_t d = r * 128 + (uint32_t)((c ^ (r & 7)) << 4);
        cp16(As + d, gA + (size_t)(m0 + r) * Kv + (size_t)it * 8 + c);
        cp16(Bs + d, gB + (size_t)(n0 + r) * Kv + (size_t)it * 8 + c);
    }
    asm volatile("cp.async.commit_group;" ::: "memory");
}

template <int EP>
__global__ __launch_bounds__(256, 2) void gemm_mma(const __nv_bfloat16* __restrict__ A,
                                                   const __nv_bfloat16* __restrict__ B,
                                                   int K, float* __restrict__ outp,
                                                   size_t out_n, int zqMode) {
    extern __shared__ __align__(16) uint8_t smem[];
    int tid = threadIdx.x, lane = tid & 31, wid = tid >> 5;
    int wm = wid & 1, wn = wid >> 1;
    int m0 = blockIdx.y * 128, n0 = blockIdx.x * 128;
    const int NIT = K >> 6;
    const int Kv  = K >> 3;

    float acc[4][4][4];
#pragma unroll
    for (int i = 0; i < 4; i++)
#pragma unroll
        for (int j = 0; j < 4; j++)
#pragma unroll
            for (int k = 0; k < 4; k++) acc[i][j][k] = 0.0f;

    const uint4* gA = (const uint4*)A;
    const uint4* gB = (const uint4*)B;

    load_tiles(smem, smem + 16384, gA, gB, m0, n0, Kv, 0, tid);

    for (int it = 0; it < NIT; it++) {
        if (it + 1 < NIT) {
            uint8_t* As = smem + ((it + 1) & 1) * 32768;
            load_tiles(As, As + 16384, gA, gB, m0, n0, Kv, it + 1, tid);
            asm volatile("cp.async.wait_group 1;" ::: "memory");
        } else {
            asm volatile("cp.async.wait_group 0;" ::: "memory");
        }
        __syncthreads();
        const uint8_t* As = smem + (it & 1) * 32768;
        const uint8_t* Bs = As + 16384;
#pragma unroll
        for (int ks = 0; ks < 4; ks++) {
            int w  = ks * 8 + (lane & 3);
            int w2 = w + 4;
            uint32_t bf[4][2];
#pragma unroll
            for (int nt = 0; nt < 4; nt++) {
                int br = wn * 32 + nt * 8 + (lane >> 2);
                bf[nt][0] = tile_word(Bs, br, w);
                bf[nt][1] = tile_word(Bs, br, w2);
            }
#pragma unroll
            for (int mt = 0; mt < 4; mt++) {
                int ar0 = wm * 64 + mt * 16 + (lane >> 2);
                int ar1 = ar0 + 8;
                uint32_t a0 = tile_word(As, ar0, w);
                uint32_t a1 = tile_word(As, ar1, w);
                uint32_t a2 = tile_word(As, ar0, w2);
                uint32_t a3 = tile_word(As, ar1, w2);
#pragma unroll
                for (int nt = 0; nt < 4; nt++)
                    mma16816(acc[mt][nt], a0, a1, a2, a3, bf[nt][0], bf[nt][1]);
            }
        }
        __syncthreads();
    }

    // ---- epilogues ----
    if (EP == 0) {
        float c1v = g_c1;
#pragma unroll
        for (int mt = 0; mt < 4; mt++) {
            int gr = m0 + wm * 64 + mt * 16 + (lane >> 2);
#pragma unroll
            for (int nt = 0; nt < 4; nt++) {
                int gc = n0 + wn * 32 + nt * 8 + (lane & 3) * 2;
                float* d0 = g_logits + (size_t)gr * NS + gc;
                float* d1 = g_logits + (size_t)(gr + 8) * NS + gc;
                d0[0] = c1v * sigmoidf_(acc[mt][nt][0]);
                d0[1] = c1v * sigmoidf_(acc[mt][nt][1]);
                d1[0] = c1v * sigmoidf_(acc[mt][nt][2]);
                d1[1] = c1v * sigmoidf_(acc[mt][nt][3]);
            }
        }
    } else if (EP == 1) {
        float s = 0.0f;
#pragma unroll
        for (int mt = 0; mt < 4; mt++)
#pragma unroll
            for (int nt = 0; nt < 4; nt++)
#pragma unroll
                for (int k = 0; k < 4; k++) s += sigmoidf_(acc[mt][nt][k]);
        double ds = (double)s;
#pragma unroll
        for (int o = 16; o > 0; o >>= 1)
            ds += __shfl_down_sync(0xffffffff, ds, o);
        if (lane == 0) atomicAdd(&g_sums[3], ds);
    } else if (EP == 2) {
        double ds = 0.0;
#pragma unroll
        for (int mt = 0; mt < 4; mt++) {
            int gr = m0 + wm * 64 + mt * 16 + (lane >> 2);
            float rn0 = g_rownorm[gr], rn1 = g_rownorm[gr + 8];
#pragma unroll
            for (int nt = 0; nt < 4; nt++) {
                int gc = n0 + wn * 32 + nt * 8 + (lane & 3) * 2;
                float cn0 = g_cbnorm[gc], cn1 = g_cbnorm[gc + 1];
                float* p0 = g_logits + (size_t)gr * NS + gc;
                float* p1 = g_logits + (size_t)(gr + 8) * NS + gc;
                float d00 = rn0 + cn0 - 2.0f * acc[mt][nt][0];
                float d01 = rn0 + cn1 - 2.0f * acc[mt][nt][1];
                float d10 = rn1 + cn0 - 2.0f * acc[mt][nt][2];
                float d11 = rn1 + cn1 - 2.0f * acc[mt][nt][3];
                float b00 = p0[0], b01 = p0[1], b10 = p1[0], b11 = p1[1];
                p0[0] = -(d00 - b00); p0[1] = -(d01 - b01);
                p1[0] = -(d10 - b10); p1[1] = -(d11 - b11);
                ds += (double)d00 + (double)d01 + (double)d10 + (double)d11;
            }
        }
#pragma unroll
        for (int o = 16; o > 0; o >>= 1)
            ds += __shfl_down_sync(0xffffffff, ds, o);
        if (lane == 0) atomicAdd(&g_sums[2], ds);
    } else { // EP == 3: z_q store
#pragma unroll
        for (int mt = 0; mt < 4; mt++) {
            int gr = m0 + wm * 64 + mt * 16 + (lane >> 2);
#pragma unroll
            for (int nt = 0; nt < 4; nt++) {
                int gc = n0 + wn * 32 + nt * 8 + (lane & 3) * 2;
#pragma unroll
                for (int k = 0; k < 4; k++) {
                    int r = gr + (k >> 1) * 8, c = gc + (k & 1);
                    size_t o;
                    bool valid = true;
                    if (zqMode == 0) {
                        o = (c < 512) ? ((size_t)r * 512 + c) * 2
                                      : ((size_t)r * 512 + (c - 512)) * 2 + 1;
                    } else if (zqMode == 1) {
                        o = (c < 512) ? ((size_t)r * 512 + c)
                                      : (8388608ULL + (size_t)r * 512 + (c - 512));
                    } else {
                        valid = (c < 512);
                        o = (size_t)r * 512 + c;
                    }
                    if (valid && o < out_n) outp[o] = acc[mt][nt][k];
                }
            }
        }
    }
}

// ---------------- softmax / entropy / argmax / gate + A3z build ----------------
__global__ __launch_bounds__(256) void softmax_kernel(const float* __restrict__ pent,
                                                      float* __restrict__ out,
                                                      size_t out_n,
                                                      size_t offProbs, size_t offHidx,
                                                      size_t offEnt) {
    __shared__ float sf[256];
    __shared__ float sv[256];
    __shared__ int   si[256];
    int row = blockIdx.x, tid = threadIdx.x;
    const float* lrow = g_logits + (size_t)row * NS;
    size_t ab = (size_t)row * 12288;

    float v[16];
    float mx = -3.4e38f;
#pragma unroll
    for (int t = 0; t < 16; t++) {
        v[t] = lrow[tid + t * 256];
        mx = fmaxf(mx, v[t]);
    }
    sf[tid] = mx; __syncthreads();
    for (int s = 128; s > 0; s >>= 1) { if (tid < s) sf[tid] = fmaxf(sf[tid], sf[tid + s]); __syncthreads(); }
    float rowmax = sf[0]; __syncthreads();

    float e[16]; float lsum = 0.0f;
#pragma unroll
    for (int t = 0; t < 16; t++) { e[t] = expf(v[t] - rowmax); lsum += e[t]; }
    sf[tid] = lsum; __syncthreads();
    for (int s = 128; s > 0; s >>= 1) { if (tid < s) sf[tid] += sf[tid + s]; __syncthreads(); }
    float rowsum = sf[0]; __syncthreads();

    float inv = 1.0f / rowsum;
    float ent = 0.0f, pm = -1.0f; int pidx = 0;
#pragma unroll
    for (int t = 0; t < 16; t++) {
        int col = tid + t * 256;
        float p = e[t] * inv;
        __nv_bfloat16 hi, lo;
        split_bf16(p, hi, lo);
        g_A3z[ab + col] = hi; g_A3z[ab + 8192 + col] = hi; g_A3z[ab + 4096 + col] = lo;
        size_t oo = offProbs + (size_t)row * NS + col;
        if (oo < out_n) out[oo] = p;
        ent -= p * logf(p + 1e-9f);
        if (p > pm) { pm = p; pidx = col; }
    }
    sf[tid] = ent; __syncthreads();
    for (int s = 128; s > 0; s >>= 1) { if (tid < s) sf[tid] += sf[tid + s]; __syncthreads(); }
    float H = sf[0]; __syncthreads();

    sv[tid] = pm; si[tid] = pidx; __syncthreads();
    for (int s = 128; s > 0; s >>= 1) {
        if (tid < s) {
            if (sv[tid + s] > sv[tid] || (sv[tid + s] == sv[tid] && si[tid + s] < si[tid])) {
                sv[tid] = sv[tid + s]; si[tid] = si[tid + s];
            }
        }
        __syncthreads();
    }
    if (tid == 0) {
        if (offHidx + row < out_n) out[offHidx + row] = (float)si[0];
        if (offEnt + row < out_n)  out[offEnt + row]  = H;
        float dH = fabsf(H - pent[row]);
        float gate = sigmoidf_((dH - 0.5f) * 10.0f);
        atomicAdd(&g_sums[4], (double)gate);
    }
}

// ---------------- anchor alignment (probs from out buffer) ----------------
__global__ __launch_bounds__(256) void anchor_kernel(const float* __restrict__ probs,
                                                     const float* __restrict__ EA,
                                                     const float* __restrict__ W,
                                                     const float* __restrict__ bv) {
    __shared__ float sB[256 * 32];
    __shared__ double sred[256];
    int warp = threadIdx.x >> 5, lane = threadIdx.x & 31;
    int r0 = blockIdx.x * 32 + warp * 4;

    float accA[4] = {0.f, 0.f, 0.f, 0.f};
    for (int c = 0; c < NS; c += 256) {
        for (int i = threadIdx.x; i < 256 * 32; i += 256) sB[i] = EA[(size_t)c * 32 + i];
        __syncthreads();
        for (int n = 0; n < 256; n++) {
            float ea = sB[n * 32 + lane];
#pragma unroll
            for (int q = 0; q < 4; q++)
                accA[q] += probs[(size_t)(r0 + q) * NS + c + n] * ea;
        }
        __syncthreads();
    }

    float accP[4];
    float bb = bv[lane];
#pragma unroll
    for (int q = 0; q < 4; q++) accP[q] = bb;
    for (int c = 0; c < KD; c += 256) {
        for (int i = threadIdx.x; i < 256 * 32; i += 256) sB[i] = W[(size_t)c * 32 + i];
        __syncthreads();
        for (int k = 0; k < 256; k++) {
            float w = sB[k * 32 + lane];
#pragma unroll
            for (int q = 0; q < 4; q++)
                accP[q] += g_flat[(size_t)(r0 + q) * KD + c + k] * w;
        }
        __syncthreads();
    }

    double s = 0.0;
#pragma unroll
    for (int q = 0; q < 4; q++) {
        float df = accP[q] - accA[q];
        s += (double)(df * df);
    }
    double r = blockReduceD(s, sred);
    if (threadIdx.x == 0) atomicAdd(&g_sums[5], r);
}

__global__ void final_kernel(float* __restrict__ out, size_t out_n,
                             size_t offDmean, size_t offAlign, size_t offTrans) {
    const double MN = (double)M_ROWS * (double)NS;
    if (offDmean < out_n) out[offDmean] = (float)(g_sums[2] / MN);
    double gateMean = g_sums[4] / 16384.0;
    if (offTrans < out_n) out[offTrans] = (float)(gateMean * ((g_sums[2] - g_sums[3]) / MN));
    if (offAlign < out_n) out[offAlign] = (float)(g_sums[5] / (16384.0 * 32.0));
}

// ---------------- host launcher ----------------
extern "C" void kernel_launch(void* const* d_in, const int* in_sizes, int n_in,
                              void* d_out, int out_size) {
    int i8a = -1, i8b = -1, i16a = -1, i16b = -1;
    int iPSD = -1, iPE = -1, iCB = -1, iEA = -1, iW = -1, iB = -1;
    for (int i = 0; i < n_in; i++) {
        int s = in_sizes[i];
        if      (s == 8388608)  { if (i8a < 0) i8a = i; else i8b = i; }
        else if (s == 16777216) { if (i16a < 0) i16a = i; else i16b = i; }
        else if (s == 67108864) iPSD = i;
        else if (s == 16384)    iPE = i;
        else if (s == 4194304)  iCB = i;
        else if (s == 131072)   iEA = i;
        else if (s == 32768)    iW = i;
        else if (s == 32)       iB = i;
    }
    const float* zr    = (const float*)d_in[i8a];
    const float* zi    = (const float*)d_in[i8b];
    const float* pprev = (const float*)d_in[iPSD];
    const float* pent  = (const float*)d_in[iPE];
    const float* cb    = (const float*)d_in[iCB];
    const float* T     = (const float*)d_in[i16a];
    const float* EA    = (const float*)d_in[iEA];
    const float* W     = (const float*)d_in[iW];
    const float* bv    = (const float*)d_in[iB];
    const float* MT    = (const float*)d_in[i16b];
    float* out = (float*)d_out;
    size_t out_n = (size_t)(unsigned int)out_size;

    const size_t OFF_DISABLED = (size_t)1 << 62;
    int zqMode; bool full;
    size_t offProbs, offHidx, offDmean, offEnt, offAlign, offTrans;
    if (out_n == 8388608ULL) {
        zqMode = 2; full = false;
        offProbs = offHidx = offDmean = offEnt = offAlign = offTrans = OFF_DISABLED;
    } else if (out_n == 16777216ULL) {
        zqMode = 1; full = false;
        offProbs = offHidx = offDmean = offEnt = offAlign = offTrans = OFF_DISABLED;
    } else if (out_n == 75530243ULL) {
        zqMode = 2; full = true;
        offProbs = 8388608ULL;
        offHidx  = offProbs + 67108864ULL;
        offDmean = offHidx + 16384ULL;
        offEnt   = offDmean + 1ULL;
        offAlign = offEnt + 16384ULL;
        offTrans = offAlign + 1ULL;
    } else {
        zqMode = 0; full = true;
        offProbs = 16777216ULL;
        offHidx  = offProbs + 67108864ULL;
        offDmean = offHidx + 16384ULL;
        offEnt   = offDmean + 1ULL;
        offAlign = offEnt + 16384ULL;
        offTrans = offAlign + 1ULL;
    }

    void *ppB16 = nullptr, *pTtB = nullptr, *pMtB = nullptr,
         *pA3d = nullptr, *pB3d = nullptr, *pA3z = nullptr, *pB3z = nullptr;
    cudaGetSymbolAddress(&ppB16, g_pB16);
    cudaGetSymbolAddress(&pTtB, g_TtB16);
    cudaGetSymbolAddress(&pMtB, g_MtB16);
    cudaGetSymbolAddress(&pA3d, g_A3d);
    cudaGetSymbolAddress(&pB3d, g_B3d);
    cudaGetSymbolAddress(&pA3z, g_A3z);
    cudaGetSymbolAddress(&pB3z, g_B3z);

    const int SMEM = 65536;
    cudaFuncSetAttribute(gemm_mma<0>, cudaFuncAttributeMaxDynamicSharedMemorySize, SMEM);
    cudaFuncSetAttribute(gemm_mma<1>, cudaFuncAttributeMaxDynamicSharedMemorySize, SMEM);
    cudaFuncSetAttribute(gemm_mma<2>, cudaFuncAttributeMaxDynamicSharedMemorySize, SMEM);
    cudaFuncSetAttribute(gemm_mma<3>, cudaFuncAttributeMaxDynamicSharedMemorySize, SMEM);

    init_kernel<<<1, 32>>>();
    prep_kernel<<<M_ROWS, 256>>>(zr, zi);
    cb_rows_kernel<<<NS, 256>>>(cb);
    c1_kernel<<<1, 1>>>();

    conv_p_kernel<<<65536, 256>>>(pprev);
    dim3 tb(32, 8);
    transpose_bf16<0><<<dim3(128, 128), tb>>>(T);
    if (full) transpose_bf16<1><<<dim3(128, 128), tb>>>(MT);
    transpose_cb_split<<<dim3(32, 128), tb>>>(cb);

    // graph bias: g_logits = c1*sigmoid(p @ T)
    gemm_mma<0><<<dim3(32, 128), 256, SMEM>>>(
        (const __nv_bfloat16*)ppB16, (const __nv_bfloat16*)pTtB, 4096, nullptr, 0, 0);
    // meta bias: sum sigmoid(p @ M)
    if (full)
        gemm_mma<1><<<dim3(32, 128), 256, SMEM>>>(
            (const __nv_bfloat16*)ppB16, (const __nv_bfloat16*)pMtB, 4096, nullptr, 0, 0);
    // d + logits (split-bf16, K=3072)
    gemm_mma<2><<<dim3(32, 128), 256, SMEM>>>(
        (const __nv_bfloat16*)pA3d, (const __nv_bfloat16*)pB3d, 3072, nullptr, 0, 0);
    // softmax + A3z build
    softmax_kernel<<<M_ROWS, 256>>>(pent, out, out_n, offProbs, offHidx, offEnt);
    // z_q (split-bf16, K=12288)
    gemm_mma<3><<<dim3(8, 128), 256, SMEM>>>(
        (const __nv_bfloat16*)pA3z, (const __nv_bfloat16*)pB3z, 12288, out, out_n, zqMode);

    if (full) {
        anchor_kernel<<<512, 256>>>(out + offProbs, EA, W, bv);
        final_kernel<<<1, 1>>>(out, out_n, offDmean, offAlign, offTrans);
    }
}